// round 10
// baseline (speedup 1.0000x reference)
#include <cuda_runtime.h>
#include <math.h>

#define BB       4096
#define SRC_LEN  128
#define IN_DIM   16
#define HH       64
#define SEQ_LEN  100
#define MEAN_DIM 4
#define COV_DIM  10

#define THREADS1 256             // 8 warps per CTA, 2 per SMSP
#define NWARP    8
#define EPW      4               // elements per warp
#define GRID1    128             // 128 * 8 * 4 = 4096
#define MEANS_OFF 0
#define COVS_OFF  (BB*SEQ_LEN*MEAN_DIM)

#define WSTRIDE   68             // padded row stride (floats) for Whh rows
#define WISTRIDE  20             // padded row stride for Wih rows
#define OWSTRIDE  68             // padded row stride for outW rows

typedef unsigned long long ull;

// decoder output scratch [B][SEQ_LEN][IN_DIM]
__device__ __align__(16) float g_dec[BB*SEQ_LEN*IN_DIM];

// ---------------------------------------------------------------------------
// f32x2 packed helpers
// ---------------------------------------------------------------------------
__device__ __forceinline__ ull pack2(float x, float y){
    ull r; asm("mov.b64 %0,{%1,%2};" : "=l"(r) : "f"(x), "f"(y)); return r;
}
__device__ __forceinline__ float2 unpack2(ull v){
    float2 r; asm("mov.b64 {%0,%1},%2;" : "=f"(r.x), "=f"(r.y) : "l"(v)); return r;
}
__device__ __forceinline__ ull fma2(ull a, ull b, ull c){
    ull d; asm("fma.rn.f32x2 %0,%1,%2,%3;" : "=l"(d) : "l"(a), "l"(b), "l"(c)); return d;
}
__device__ __forceinline__ float tanhapx(float x){
    float y; asm("tanh.approx.f32 %0,%1;" : "=f"(y) : "f"(x)); return y;
}
// sigmoid(x) = 0.5 + 0.5*tanh(0.5x)  (1 MUFU)
__device__ __forceinline__ float sigm(float x){
    return fmaf(tanhapx(0.5f*x), 0.5f, 0.5f);
}

// ---------------------------------------------------------------------------
// SMEM (~84 KB dynamic)
// per-warp h layout: hv2[j*2 + p] (j = h-row, p = elem-pair 0/1)
// per-warp x layout: xv2[d*2 + p]
// ---------------------------------------------------------------------------
struct Smem {
    __align__(16) float wT [192*WSTRIDE];     // Whh rows, padded stride
    __align__(16) float wiT[192*WISTRIDE];    // Wih rows, padded stride
    __align__(16) float outw[16*OWSTRIDE];    // outW rows, padded stride
    __align__(16) ull   h2[NWARP][HH*2];
    __align__(16) ull   x2[NWARP][2][IN_DIM*2];
};

// ---------------------------------------------------------------------------
// Gate accumulation: rows (lane, lane+32), 2 elem-pairs. 12 fma2 per k.
// ---------------------------------------------------------------------------
template<int NKQ, int RS, int UNROLL>
__device__ __forceinline__ void gates_accum4(
    const float* __restrict__ w, const ull* __restrict__ v, int lane,
    ull aR[2][2], ull aZ[2][2], ull aN[2][2])
{
    #pragma unroll UNROLL
    for(int kq = 0; kq < NKQ; kq++){
        float4 wra = *(const float4*)(w + (      lane)*RS + kq*4);
        float4 wrb = *(const float4*)(w + ( 32 + lane)*RS + kq*4);
        float4 wza = *(const float4*)(w + ( 64 + lane)*RS + kq*4);
        float4 wzb = *(const float4*)(w + ( 96 + lane)*RS + kq*4);
        float4 wna = *(const float4*)(w + (128 + lane)*RS + kq*4);
        float4 wnb = *(const float4*)(w + (160 + lane)*RS + kq*4);
        #pragma unroll
        for(int i = 0; i < 4; i++){
            int k = kq*4 + i;
            ulonglong2 v01 = *(const ulonglong2*)(v + k*2);
            float fra=(&wra.x)[i], frb=(&wrb.x)[i];
            float fza=(&wza.x)[i], fzb=(&wzb.x)[i];
            float fna=(&wna.x)[i], fnb=(&wnb.x)[i];
            ull ra=pack2(fra,fra), rb=pack2(frb,frb);
            ull za=pack2(fza,fza), zb=pack2(fzb,fzb);
            ull na=pack2(fna,fna), nb=pack2(fnb,fnb);
            aR[0][0]=fma2(v01.x,ra,aR[0][0]); aR[0][1]=fma2(v01.y,ra,aR[0][1]);
            aR[1][0]=fma2(v01.x,rb,aR[1][0]); aR[1][1]=fma2(v01.y,rb,aR[1][1]);
            aZ[0][0]=fma2(v01.x,za,aZ[0][0]); aZ[0][1]=fma2(v01.y,za,aZ[0][1]);
            aZ[1][0]=fma2(v01.x,zb,aZ[1][0]); aZ[1][1]=fma2(v01.y,zb,aZ[1][1]);
            aN[0][0]=fma2(v01.x,na,aN[0][0]); aN[0][1]=fma2(v01.y,na,aN[0][1]);
            aN[1][0]=fma2(v01.x,nb,aN[1][0]); aN[1][1]=fma2(v01.y,nb,aN[1][1]);
        }
    }
}

// One GRU step for this warp's 4 elements.
__device__ __forceinline__ void gru_step(
    const float* __restrict__ wiT, const float* __restrict__ wT,
    ull* __restrict__ hv2, const ull* __restrict__ xv2, int lane,
    const ull br2[2], const ull bz2[2], const ull bni2[2], const ull bnh2[2])
{
    ull aR[2][2], aZ[2][2], aNi[2][2], aHn[2][2];
    #pragma unroll
    for(int rr = 0; rr < 2; rr++){
        #pragma unroll
        for(int p = 0; p < 2; p++){
            aR[rr][p]=br2[rr]; aZ[rr][p]=bz2[rr];
            aNi[rr][p]=bni2[rr]; aHn[rr][p]=bnh2[rr];
        }
    }
    gates_accum4<IN_DIM/4, WISTRIDE, 4>(wiT, xv2, lane, aR, aZ, aNi);
    gates_accum4<HH/4,     WSTRIDE,  4>(wT,  hv2, lane, aR, aZ, aHn);

    // read old h for own rows
    ulonglong2 old[2];
    #pragma unroll
    for(int rr = 0; rr < 2; rr++){
        int j = lane + rr*32;
        old[rr] = *(const ulonglong2*)(hv2 + j*2);
    }
    __syncwarp();    // gate reads of h complete

    #pragma unroll
    for(int rr = 0; rr < 2; rr++){
        int j = lane + rr*32;
        float hold[4];
        { float2 t;
          t=unpack2(old[rr].x); hold[0]=t.x; hold[1]=t.y;
          t=unpack2(old[rr].y); hold[2]=t.x; hold[3]=t.y; }
        float hn[4];
        #pragma unroll
        for(int p = 0; p < 2; p++){
            float2 r2  = unpack2(aR[rr][p]),  z2  = unpack2(aZ[rr][p]);
            float2 ni2 = unpack2(aNi[rr][p]), nh2 = unpack2(aHn[rr][p]);
            float r0 = sigm(r2.x), r1 = sigm(r2.y);
            float z0 = sigm(z2.x), z1 = sigm(z2.y);
            float n0 = tanhapx(fmaf(r0, nh2.x, ni2.x));
            float n1 = tanhapx(fmaf(r1, nh2.y, ni2.y));
            hn[2*p]   = fmaf(z0, hold[2*p]   - n0, n0);
            hn[2*p+1] = fmaf(z1, hold[2*p+1] - n1, n1);
        }
        ulonglong2 sN;
        sN.x = pack2(hn[0],hn[1]); sN.y = pack2(hn[2],hn[3]);
        *(ulonglong2*)(hv2 + j*2) = sN;
    }
    __syncwarp();    // h writes visible
}

// ---------------------------------------------------------------------------
// Kernel 1: encoder (128 steps) + decoder (100 steps), warp-autonomous
// ---------------------------------------------------------------------------
__global__ void __launch_bounds__(THREADS1, 1) seq_kernel(
    const float* __restrict__ x,    const float* __restrict__ trg,
    const float* __restrict__ eWih, const float* __restrict__ ebih,
    const float* __restrict__ eWhh, const float* __restrict__ ebhh,
    const float* __restrict__ dWih, const float* __restrict__ dbih,
    const float* __restrict__ dWhh, const float* __restrict__ dbhh,
    const float* __restrict__ outW, const float* __restrict__ outb,
    const float* __restrict__ embW, const float* __restrict__ embb)
{
    extern __shared__ unsigned char smem_raw[];
    Smem& s = *reinterpret_cast<Smem*>(smem_raw);
    const int tid  = threadIdx.x;
    const int w    = tid >> 5;
    const int lane = tid & 31;
    const int warpB = (blockIdx.x*NWARP + w)*EPW;   // base batch index

    // ---- stage encoder weights (row-native, padded stride) ----
    for(int i = tid; i < 192*HH; i += THREADS1){
        int r = i >> 6, k = i & 63;
        s.wT[r*WSTRIDE + k] = eWhh[i];
    }
    for(int i = tid; i < 192*IN_DIM; i += THREADS1){
        int r = i >> 4, d = i & 15;
        s.wiT[r*WISTRIDE + d] = eWih[i];
    }
    for(int i = tid; i < 16*HH; i += THREADS1){
        int dd = i >> 6, k = i & 63;
        s.outw[dd*OWSTRIDE + k] = outW[i];
    }
    __syncthreads();

    ull* hv2 = s.h2[w];

    // zero own h rows
    #pragma unroll
    for(int rr = 0; rr < 2; rr++){
        int j = lane + rr*32;
        ulonglong2 z; z.x = 0ull; z.y = 0ull;
        *(ulonglong2*)(hv2 + j*2) = z;
    }

    // packed encoder biases
    ull br2[2], bz2[2], bni2[2], bnh2[2];
    #pragma unroll
    for(int rr = 0; rr < 2; rr++){
        int j = lane + rr*32;
        float br = ebih[j] + ebhh[j];
        float bz = ebih[64+j] + ebhh[64+j];
        br2[rr]  = pack2(br, br);
        bz2[rr]  = pack2(bz, bz);
        bni2[rr] = pack2(ebih[128+j], ebih[128+j]);
        bnh2[rr] = pack2(ebhh[128+j], ebhh[128+j]);
    }

    // x gather mapping: lane -> (elem e = lane>>3, dims d0, d0+1)
    const int e  = lane >> 3;           // 0..3
    const int d0 = (lane & 7) * 2;      // 0,2,..,14
    const float* xbase = x + ((size_t)(warpB + e)*SRC_LEN)*IN_DIM + d0;

    // preload x[0] into buf 0
    {
        float2 xv = *(const float2*)xbase;
        float* xf0 = (float*)s.x2[w][0];
        xf0[(d0+0)*4 + e] = xv.x;
        xf0[(d0+1)*4 + e] = xv.y;
    }
    __syncwarp();

    // ================= encoder =================
    for(int t = 0; t < SRC_LEN; t++){
        int cur = t & 1, nxt = cur ^ 1;
        if(t + 1 < SRC_LEN){
            float2 xv = *(const float2*)(xbase + (size_t)(t+1)*IN_DIM);
            float* xfn = (float*)s.x2[w][nxt];
            xfn[(d0+0)*4 + e] = xv.x;
            xfn[(d0+1)*4 + e] = xv.y;
        }
        gru_step(s.wiT, s.wT, hv2, s.x2[w][cur], lane, br2, bz2, bni2, bnh2);
    }

    // ---- switch to decoder weights ----
    __syncthreads();
    for(int i = tid; i < 192*HH; i += THREADS1){
        int r = i >> 6, k = i & 63;
        s.wT[r*WSTRIDE + k] = dWhh[i];
    }
    for(int i = tid; i < 192*IN_DIM; i += THREADS1){
        int r = i >> 4, d = i & 15;
        s.wiT[r*WISTRIDE + d] = dWih[i];
    }
    __syncthreads();

    // decoder biases
    #pragma unroll
    for(int rr = 0; rr < 2; rr++){
        int j = lane + rr*32;
        float br = dbih[j] + dbhh[j];
        float bz = dbih[64+j] + dbhh[64+j];
        br2[rr]  = pack2(br, br);
        bz2[rr]  = pack2(bz, bz);
        bni2[rr] = pack2(dbih[128+j], dbih[128+j]);
        bnh2[rr] = pack2(dbhh[128+j], dbhh[128+j]);
    }

    // initial decoder input: emb(trg) -> buf 0
    if(lane < 16){
        int ee = lane >> 2;             // 0..3
        int dbase = (lane & 3) * 4;     // 0,4,8,12
        float4 tv = *(const float4*)(trg + (size_t)(warpB + ee)*4);
        float* xf0 = (float*)s.x2[w][0];
        #pragma unroll
        for(int i = 0; i < 4; i++){
            int d = dbase + i;
            float a = embb[d] + embW[d*4+0]*tv.x + embW[d*4+1]*tv.y
                              + embW[d*4+2]*tv.z + embW[d*4+3]*tv.w;
            xf0[d*4 + ee] = a;
        }
    }
    const int dd = lane >> 1;          // out dim 0..15
    const int pp = lane & 1;           // elem-pair (0 or 1)
    const float ob = outb[dd];
    __syncwarp();

    // ================= decoder =================
    for(int t = 0; t < SEQ_LEN; t++){
        int cur = t & 1, nxt = cur ^ 1;
        gru_step(s.wiT, s.wT, hv2, s.x2[w][cur], lane, br2, bz2, bni2, bnh2);

        // out projection: lane computes o[dd] for its elem-pair (2 elems)
        ull o2 = pack2(ob, ob);
        #pragma unroll 4
        for(int kq = 0; kq < 16; kq++){
            float4 wv4 = *(const float4*)(s.outw + dd*OWSTRIDE + kq*4);
            #pragma unroll
            for(int i = 0; i < 4; i++){
                int k = kq*4 + i;
                ull hp = hv2[k*2 + pp];
                float wv = (&wv4.x)[i];
                o2 = fma2(hp, pack2(wv, wv), o2);
            }
        }
        float2 oa = unpack2(o2);
        int e0 = pp*2;
        float* xfn = (float*)s.x2[w][nxt];
        xfn[dd*4 + e0]     = oa.x;
        xfn[dd*4 + e0 + 1] = oa.y;
        size_t gb = ((size_t)(warpB + e0)*SEQ_LEN + t)*IN_DIM + dd;
        const size_t ES = (size_t)SEQ_LEN*IN_DIM;
        g_dec[gb]      = oa.x;
        g_dec[gb + ES] = oa.y;
        __syncwarp();
    }
}

// ---------------------------------------------------------------------------
// A&S 7.1.26 erf-based exact GELU (|erf err| <= 1.5e-7)
// ---------------------------------------------------------------------------
__device__ __forceinline__ float gelu_exact(float x){
    const float A1 =  0.254829592f, A2 = -0.284496736f, A3 = 1.421413741f;
    const float A4 = -1.453152027f, A5 =  1.061405429f, P  = 0.3275911f;
    float sarg = 0.70710678118654752f * x;
    float a = fabsf(sarg);
    float t = __fdividef(1.f, fmaf(P, a, 1.f));
    float poly = t*fmaf(t, fmaf(t, fmaf(t, fmaf(t, A5, A4), A3), A2), A1);
    float erf = fmaf(-poly, __expf(-a*a), 1.f);
    erf = copysignf(erf, sarg);
    return 0.5f * x * (1.f + erf);
}

// ---------------------------------------------------------------------------
// Kernel 2: output heads, 2 rows per thread, f32x2
// ---------------------------------------------------------------------------
__global__ void __launch_bounds__(256) heads_kernel(
    const float* __restrict__ mhW1, const float* __restrict__ mhb1,
    const float* __restrict__ mhW2, const float* __restrict__ mhb2,
    const float* __restrict__ chW1, const float* __restrict__ chb1,
    const float* __restrict__ chW2, const float* __restrict__ chb2,
    float* __restrict__ out)
{
    __shared__ __align__(16) float w1m[HH*IN_DIM], w1c[HH*IN_DIM];
    __shared__ __align__(16) ull  w2mP[HH*2];
    __shared__ __align__(16) ull  w2cP[HH*5];
    __shared__ float b1m[HH], b1c[HH];
    __shared__ float b2m[MEAN_DIM], b2c[COV_DIM];

    int tid = threadIdx.x;
    for(int i = tid; i < HH*IN_DIM; i += 256){ w1m[i] = mhW1[i]; w1c[i] = chW1[i]; }
    for(int i = tid; i < HH*2; i += 256){
        int u = i >> 1, mp = i & 1;
        w2mP[i] = pack2(mhW2[(2*mp)*HH + u], mhW2[(2*mp+1)*HH + u]);
    }
    for(int i = tid; i < HH*5; i += 256){
        int u = i / 5, vp = i - u*5;
        w2cP[i] = pack2(chW2[(2*vp)*HH + u], chW2[(2*vp+1)*HH + u]);
    }
    if(tid < HH){ b1m[tid] = mhb1[tid]; b1c[tid] = chb1[tid]; }
    if(tid < MEAN_DIM) b2m[tid] = mhb2[tid];
    if(tid < COV_DIM)  b2c[tid] = chb2[tid];
    __syncthreads();

    int r0 = (blockIdx.x*256 + tid)*2;      // rows r0, r0+1
    const ulonglong2* opA = (const ulonglong2*)&g_dec[(size_t)r0*IN_DIM];
    ulonglong2 qa0 = opA[0], qa1 = opA[1], qa2 = opA[2], qa3 = opA[3];
    ulonglong2 qb0 = opA[4], qb1 = opA[5], qb2 = opA[6], qb3 = opA[7];
    ull ovA[8] = { qa0.x,qa0.y,qa1.x,qa1.y,qa2.x,qa2.y,qa3.x,qa3.y };
    ull ovB[8] = { qb0.x,qb0.y,qb1.x,qb1.y,qb2.x,qb2.y,qb3.x,qb3.y };

    ull amA[2], amB[2], acA[5], acB[5];
    amA[0] = amB[0] = pack2(b2m[0], b2m[1]);
    amA[1] = amB[1] = pack2(b2m[2], b2m[3]);
    #pragma unroll
    for(int vp = 0; vp < 5; vp++) acA[vp] = acB[vp] = pack2(b2c[2*vp], b2c[2*vp+1]);

    #pragma unroll 4
    for(int u = 0; u < HH; u++){
        const ull* w1mp = (const ull*)(w1m + u*16);
        const ull* w1cp = (const ull*)(w1c + u*16);
        ull a1A = 0, a1B = 0, a2A = 0, a2B = 0;
        #pragma unroll
        for(int i = 0; i < 8; i++){
            ull wm = w1mp[i], wc = w1cp[i];
            a1A = fma2(ovA[i], wm, a1A);
            a1B = fma2(ovB[i], wm, a1B);
            a2A = fma2(ovA[i], wc, a2A);
            a2B = fma2(ovB[i], wc, a2B);
        }
        float2 f;
        f = unpack2(a1A); float s1A = b1m[u] + f.x + f.y;
        f = unpack2(a1B); float s1B = b1m[u] + f.x + f.y;
        f = unpack2(a2A); float s2A = b1c[u] + f.x + f.y;
        f = unpack2(a2B); float s2B = b1c[u] + f.x + f.y;
        float g1A = gelu_exact(s1A), g1B = gelu_exact(s1B);
        float g2A = gelu_exact(s2A), g2B = gelu_exact(s2B);
        ull g1Ap = pack2(g1A, g1A), g1Bp = pack2(g1B, g1B);
        ull g2Ap = pack2(g2A, g2A), g2Bp = pack2(g2B, g2B);
        ull wm0 = w2mP[u*2], wm1 = w2mP[u*2+1];
        amA[0] = fma2(g1Ap, wm0, amA[0]); amA[1] = fma2(g1Ap, wm1, amA[1]);
        amB[0] = fma2(g1Bp, wm0, amB[0]); amB[1] = fma2(g1Bp, wm1, amB[1]);
        #pragma unroll
        for(int vp = 0; vp < 5; vp++){
            ull wcv = w2cP[u*5+vp];
            acA[vp] = fma2(g2Ap, wcv, acA[vp]);
            acB[vp] = fma2(g2Bp, wcv, acB[vp]);
        }
    }

    // clamp means dims 2,3 to [-1,1]
    { float2 m = unpack2(amA[1]);
      m.x = fminf(fmaxf(m.x, -1.f), 1.f); m.y = fminf(fmaxf(m.y, -1.f), 1.f);
      amA[1] = pack2(m.x, m.y); }
    { float2 m = unpack2(amB[1]);
      m.x = fminf(fmaxf(m.x, -1.f), 1.f); m.y = fminf(fmaxf(m.y, -1.f), 1.f);
      amB[1] = pack2(m.x, m.y); }

    ull* om = (ull*)(out + MEANS_OFF) + (size_t)r0*2;
    om[0] = amA[0]; om[1] = amA[1]; om[2] = amB[0]; om[3] = amB[1];
    ull* oc = (ull*)(out + COVS_OFF) + (size_t)r0*5;
    #pragma unroll
    for(int vp = 0; vp < 5; vp++){ oc[vp] = acA[vp]; oc[5+vp] = acB[vp]; }
}

// ---------------------------------------------------------------------------
extern "C" void kernel_launch(void* const* d_in, const int* in_sizes, int n_in,
                              void* d_out, int out_size)
{
    const float* x     = (const float*)d_in[0];
    const float* trg   = (const float*)d_in[1];
    const float* eWih  = (const float*)d_in[2];
    const float* ebih  = (const float*)d_in[3];
    const float* eWhh  = (const float*)d_in[4];
    const float* ebhh  = (const float*)d_in[5];
    const float* dWih  = (const float*)d_in[6];
    const float* dbih  = (const float*)d_in[7];
    const float* dWhh  = (const float*)d_in[8];
    const float* dbhh  = (const float*)d_in[9];
    const float* outW  = (const float*)d_in[10];
    const float* outb  = (const float*)d_in[11];
    const float* embW  = (const float*)d_in[12];
    const float* embb  = (const float*)d_in[13];
    const float* mhW1  = (const float*)d_in[14];
    const float* mhb1  = (const float*)d_in[15];
    const float* mhW2  = (const float*)d_in[16];
    const float* mhb2  = (const float*)d_in[17];
    const float* chW1  = (const float*)d_in[18];
    const float* chb1  = (const float*)d_in[19];
    const float* chW2  = (const float*)d_in[20];
    const float* chb2  = (const float*)d_in[21];

    cudaFuncSetAttribute(seq_kernel, cudaFuncAttributeMaxDynamicSharedMemorySize,
                         (int)sizeof(Smem));

    seq_kernel<<<GRID1, THREADS1, sizeof(Smem)>>>(
        x, trg, eWih, ebih, eWhh, ebhh, dWih, dbih, dWhh, dbhh,
        outW, outb, embW, embb);

    heads_kernel<<<(BB*SEQ_LEN)/512, 256>>>(
        mhW1, mhb1, mhW2, mhb2, chW1, chb1, chW2, chb2, (float*)d_out);
}

// round 11
// speedup vs baseline: 1.0430x; 1.0430x over previous
#include <cuda_runtime.h>
#include <math.h>

#define BB       4096
#define SRC_LEN  128
#define IN_DIM   16
#define HH       64
#define SEQ_LEN  100
#define MEAN_DIM 4
#define COV_DIM  10

#define THREADS1 256             // 8 warps = 4 pairs per CTA
#define NPAIR    4
#define EPP      8               // batch elements per pair
#define GRID1    128             // 128 * 4 * 8 = 4096
#define MEANS_OFF 0
#define COVS_OFF  (BB*SEQ_LEN*MEAN_DIM)

#define WSTRIDE   68             // padded row stride (floats) for Whh rows
#define WISTRIDE  20             // padded row stride for Wih rows
#define OWSTRIDE  68             // padded row stride for outW rows

typedef unsigned long long ull;

// decoder output scratch [B][SEQ_LEN][IN_DIM]
__device__ __align__(16) float g_dec[BB*SEQ_LEN*IN_DIM];

// pair barrier: named barrier (1+p), 64 threads
#define PBAR(p) asm volatile("bar.sync %0, 64;" :: "r"(1+(p)) : "memory")

// ---------------------------------------------------------------------------
// f32x2 packed helpers
// ---------------------------------------------------------------------------
__device__ __forceinline__ ull pack2(float x, float y){
    ull r; asm("mov.b64 %0,{%1,%2};" : "=l"(r) : "f"(x), "f"(y)); return r;
}
__device__ __forceinline__ float2 unpack2(ull v){
    float2 r; asm("mov.b64 {%0,%1},%2;" : "=f"(r.x), "=f"(r.y) : "l"(v)); return r;
}
__device__ __forceinline__ ull fma2(ull a, ull b, ull c){
    ull d; asm("fma.rn.f32x2 %0,%1,%2,%3;" : "=l"(d) : "l"(a), "l"(b), "l"(c)); return d;
}
__device__ __forceinline__ float tanhapx(float x){
    float y; asm("tanh.approx.f32 %0,%1;" : "=f"(y) : "f"(x)); return y;
}
// sigmoid(x) = 0.5 + 0.5*tanh(0.5x)  (1 MUFU)
__device__ __forceinline__ float sigm(float x){
    return fmaf(tanhapx(0.5f*x), 0.5f, 0.5f);
}

// ---------------------------------------------------------------------------
// SMEM (~92 KB dynamic)
// per-pair h layout: h2[pair][buf][k*4 + p]  (k = h-row, p = elem-pair 0..3)
// per-pair x layout: x2[pair][buf][d*4 + p]
// ---------------------------------------------------------------------------
struct Smem {
    __align__(16) float wT [192*WSTRIDE];     // Whh rows, padded stride
    __align__(16) float wiT[192*WISTRIDE];    // Wih rows, padded stride
    __align__(16) float outw[16*OWSTRIDE];    // outW rows, padded stride
    __align__(16) ull   h2[NPAIR][2][HH*4];   // double-buffered h state
    __align__(16) ull   x2[NPAIR][2][IN_DIM*4];
};

// ---------------------------------------------------------------------------
// Gate accumulation for ONE gate-row-triple (r/z/n rows of this lane's j).
// 12 fma2 per k, over all 4 elem-pairs.
// ---------------------------------------------------------------------------
template<int NKQ, int UNROLL>
__device__ __forceinline__ void gates_accum(
    const float* __restrict__ wr, const float* __restrict__ wz,
    const float* __restrict__ wn, const ull* __restrict__ v,
    ull aR[4], ull aZ[4], ull aN[4])
{
    #pragma unroll UNROLL
    for(int kq = 0; kq < NKQ; kq++){
        float4 wr4 = *(const float4*)(wr + kq*4);
        float4 wz4 = *(const float4*)(wz + kq*4);
        float4 wn4 = *(const float4*)(wn + kq*4);
        #pragma unroll
        for(int i = 0; i < 4; i++){
            int k = kq*4 + i;
            ulonglong2 v01 = *(const ulonglong2*)(v + k*4);
            ulonglong2 v23 = *(const ulonglong2*)(v + k*4 + 2);
            float fr = (&wr4.x)[i], fz = (&wz4.x)[i], fn = (&wn4.x)[i];
            ull rp = pack2(fr, fr), zp = pack2(fz, fz), np = pack2(fn, fn);
            aR[0]=fma2(v01.x,rp,aR[0]); aR[1]=fma2(v01.y,rp,aR[1]);
            aR[2]=fma2(v23.x,rp,aR[2]); aR[3]=fma2(v23.y,rp,aR[3]);
            aZ[0]=fma2(v01.x,zp,aZ[0]); aZ[1]=fma2(v01.y,zp,aZ[1]);
            aZ[2]=fma2(v23.x,zp,aZ[2]); aZ[3]=fma2(v23.y,zp,aZ[3]);
            aN[0]=fma2(v01.x,np,aN[0]); aN[1]=fma2(v01.y,np,aN[1]);
            aN[2]=fma2(v23.x,np,aN[2]); aN[3]=fma2(v23.y,np,aN[3]);
        }
    }
}

// One GRU step: this lane computes h_new[j] for its pair's 8 elements.
// Reads h from hcur (broadcast), writes h_new into hnxt. No sync inside.
__device__ __forceinline__ void gru_step(
    const float* __restrict__ wrih, const float* __restrict__ wzih,
    const float* __restrict__ wnih,
    const float* __restrict__ wrhh, const float* __restrict__ wzhh,
    const float* __restrict__ wnhh,
    const ull* __restrict__ hcur, ull* __restrict__ hnxt,
    const ull* __restrict__ xcur, int j,
    ull br2, ull bz2, ull bni2, ull bnh2)
{
    ull aR[4], aZ[4], aNi[4], aHn[4];
    #pragma unroll
    for(int p = 0; p < 4; p++){
        aR[p]=br2; aZ[p]=bz2; aNi[p]=bni2; aHn[p]=bnh2;
    }
    gates_accum<IN_DIM/4, 4>(wrih, wzih, wnih, xcur, aR, aZ, aNi);
    gates_accum<HH/4,     4>(wrhh, wzhh, wnhh, hcur, aR, aZ, aHn);

    // old h for own row j
    ulonglong2 o01 = *(const ulonglong2*)(hcur + j*4);
    ulonglong2 o23 = *(const ulonglong2*)(hcur + j*4 + 2);
    float hold[4+4];
    { float2 t;
      t=unpack2(o01.x); hold[0]=t.x; hold[1]=t.y;
      t=unpack2(o01.y); hold[2]=t.x; hold[3]=t.y;
      t=unpack2(o23.x); hold[4]=t.x; hold[5]=t.y;
      t=unpack2(o23.y); hold[6]=t.x; hold[7]=t.y; }

    float hn[8];
    #pragma unroll
    for(int p = 0; p < 4; p++){
        float2 r2  = unpack2(aR[p]),  z2  = unpack2(aZ[p]);
        float2 ni2 = unpack2(aNi[p]), nh2 = unpack2(aHn[p]);
        float r0 = sigm(r2.x), r1 = sigm(r2.y);
        float z0 = sigm(z2.x), z1 = sigm(z2.y);
        float n0 = tanhapx(fmaf(r0, nh2.x, ni2.x));
        float n1 = tanhapx(fmaf(r1, nh2.y, ni2.y));
        hn[2*p]   = fmaf(z0, hold[2*p]   - n0, n0);
        hn[2*p+1] = fmaf(z1, hold[2*p+1] - n1, n1);
    }
    ulonglong2 s01, s23;
    s01.x = pack2(hn[0],hn[1]); s01.y = pack2(hn[2],hn[3]);
    s23.x = pack2(hn[4],hn[5]); s23.y = pack2(hn[6],hn[7]);
    *(ulonglong2*)(hnxt + j*4)     = s01;
    *(ulonglong2*)(hnxt + j*4 + 2) = s23;
}

// ---------------------------------------------------------------------------
// Kernel 1: encoder (128 steps) + decoder (100 steps), warp-pair row split
// ---------------------------------------------------------------------------
__global__ void __launch_bounds__(THREADS1, 1) seq_kernel(
    const float* __restrict__ x,    const float* __restrict__ trg,
    const float* __restrict__ eWih, const float* __restrict__ ebih,
    const float* __restrict__ eWhh, const float* __restrict__ ebhh,
    const float* __restrict__ dWih, const float* __restrict__ dbih,
    const float* __restrict__ dWhh, const float* __restrict__ dbhh,
    const float* __restrict__ outW, const float* __restrict__ outb,
    const float* __restrict__ embW, const float* __restrict__ embb)
{
    extern __shared__ unsigned char smem_raw[];
    Smem& s = *reinterpret_cast<Smem*>(smem_raw);
    const int tid   = threadIdx.x;
    const int wid   = tid >> 5;
    const int lane  = tid & 31;
    const int pr    = wid >> 1;          // pair 0..3
    const int sub   = wid & 1;           // row-half within pair
    const int tid64 = sub*32 + lane;     // 0..63 within pair
    const int j     = tid64;             // this lane's gate row 0..63
    const int pairB = (blockIdx.x*NPAIR + pr)*EPP;   // base batch index

    // ---- stage encoder weights (row-native, padded stride) ----
    for(int i = tid; i < 192*HH; i += THREADS1){
        int r = i >> 6, k = i & 63;
        s.wT[r*WSTRIDE + k] = eWhh[i];
    }
    for(int i = tid; i < 192*IN_DIM; i += THREADS1){
        int r = i >> 4, d = i & 15;
        s.wiT[r*WISTRIDE + d] = eWih[i];
    }
    for(int i = tid; i < 16*HH; i += THREADS1){
        int dd = i >> 6, k = i & 63;
        s.outw[dd*OWSTRIDE + k] = outW[i];
    }

    // weight row pointers for this lane's gate rows (j, 64+j, 128+j)
    const float* wrhh = s.wT + (      j)*WSTRIDE;
    const float* wzhh = s.wT + ( 64 + j)*WSTRIDE;
    const float* wnhh = s.wT + (128 + j)*WSTRIDE;
    const float* wrih = s.wiT + (      j)*WISTRIDE;
    const float* wzih = s.wiT + ( 64 + j)*WISTRIDE;
    const float* wnih = s.wiT + (128 + j)*WISTRIDE;

    // zero h buffer 0 (whole pair region, split across pair threads)
    {
        ull* hb = s.h2[pr][0];
        for(int i = tid64; i < HH*4; i += 64) hb[i] = 0ull;
    }
    __syncthreads();

    // packed encoder biases for row j
    ull br2  = pack2(ebih[j] + ebhh[j],       ebih[j] + ebhh[j]);
    ull bz2  = pack2(ebih[64+j] + ebhh[64+j], ebih[64+j] + ebhh[64+j]);
    ull bni2 = pack2(ebih[128+j], ebih[128+j]);
    ull bnh2 = pack2(ebhh[128+j], ebhh[128+j]);

    // x gather mapping: tid64 -> (elem e, dims d0, d0+1)
    const int e  = tid64 >> 3;           // 0..7
    const int d0 = (tid64 & 7) * 2;      // 0,2,..,14
    const float* xbase = x + ((size_t)(pairB + e)*SRC_LEN)*IN_DIM + d0;

    // preload x[0] into buf 0
    {
        float2 xv = *(const float2*)xbase;
        float* xf0 = (float*)s.x2[pr][0];
        xf0[(d0+0)*8 + e] = xv.x;
        xf0[(d0+1)*8 + e] = xv.y;
    }
    PBAR(pr);

    int cur = 0;

    // ================= encoder =================
    for(int t = 0; t < SRC_LEN; t++){
        int nxt = cur ^ 1;
        if(t + 1 < SRC_LEN){
            float2 xv = *(const float2*)(xbase + (size_t)(t+1)*IN_DIM);
            float* xfn = (float*)s.x2[pr][nxt];
            xfn[(d0+0)*8 + e] = xv.x;
            xfn[(d0+1)*8 + e] = xv.y;
        }
        gru_step(wrih, wzih, wnih, wrhh, wzhh, wnhh,
                 s.h2[pr][cur], s.h2[pr][nxt], s.x2[pr][cur], j,
                 br2, bz2, bni2, bnh2);
        PBAR(pr);
        cur = nxt;
    }
    // cur == 0 again (128 flips), final encoder h in h2[pr][0]

    // ---- switch to decoder weights ----
    __syncthreads();
    for(int i = tid; i < 192*HH; i += THREADS1){
        int r = i >> 6, k = i & 63;
        s.wT[r*WSTRIDE + k] = dWhh[i];
    }
    for(int i = tid; i < 192*IN_DIM; i += THREADS1){
        int r = i >> 4, d = i & 15;
        s.wiT[r*WISTRIDE + d] = dWih[i];
    }

    // decoder biases
    br2  = pack2(dbih[j] + dbhh[j],       dbih[j] + dbhh[j]);
    bz2  = pack2(dbih[64+j] + dbhh[64+j], dbih[64+j] + dbhh[64+j]);
    bni2 = pack2(dbih[128+j], dbih[128+j]);
    bnh2 = pack2(dbhh[128+j], dbhh[128+j]);

    // initial decoder input: emb(trg) -> x buf 0
    {
        float2 tv01 = *(const float2*)(trg + (size_t)(pairB + e)*4);
        float2 tv23 = *(const float2*)(trg + (size_t)(pairB + e)*4 + 2);
        float* xf0 = (float*)s.x2[pr][0];
        #pragma unroll
        for(int i = 0; i < 2; i++){
            int d = d0 + i;
            float a = embb[d] + embW[d*4+0]*tv01.x + embW[d*4+1]*tv01.y
                              + embW[d*4+2]*tv23.x + embW[d*4+3]*tv23.y;
            xf0[d*8 + e] = a;
        }
    }

    // out-proj mapping: tid64 -> (out dim dd, elem-pair op)
    const int dd = tid64 >> 2;          // 0..15
    const int op = tid64 & 3;           // 0..3
    const float ob = outb[dd];
    const float* owrow = s.outw + dd*OWSTRIDE;
    __syncthreads();

    // ================= decoder =================
    for(int t = 0; t < SEQ_LEN; t++){
        int nxt = cur ^ 1;
        gru_step(wrih, wzih, wnih, wrhh, wzhh, wnhh,
                 s.h2[pr][cur], s.h2[pr][nxt], s.x2[pr][cur], j,
                 br2, bz2, bni2, bnh2);
        PBAR(pr);    // h_new complete (both halves)

        // out projection: o[dd] for elem-pair op (2 elements)
        const ull* hnew = s.h2[pr][nxt];
        ull o2 = pack2(ob, ob);
        #pragma unroll 4
        for(int kq = 0; kq < 16; kq++){
            float4 w4 = *(const float4*)(owrow + kq*4);
            #pragma unroll
            for(int i = 0; i < 4; i++){
                int k = kq*4 + i;
                ull hp = hnew[k*4 + op];
                float wv = (&w4.x)[i];
                o2 = fma2(hp, pack2(wv, wv), o2);
            }
        }
        // feed back as next x + store to g_dec
        s.x2[pr][nxt][dd*4 + op] = o2;
        float2 oa = unpack2(o2);
        int b0 = pairB + 2*op;
        size_t gb = ((size_t)b0*SEQ_LEN + t)*IN_DIM + dd;
        const size_t ES = (size_t)SEQ_LEN*IN_DIM;
        g_dec[gb]      = oa.x;
        g_dec[gb + ES] = oa.y;
        PBAR(pr);    // x_next complete
        cur = nxt;
    }
}

// ---------------------------------------------------------------------------
// A&S 7.1.26 erf-based exact GELU (|erf err| <= 1.5e-7)
// ---------------------------------------------------------------------------
__device__ __forceinline__ float gelu_exact(float x){
    const float A1 =  0.254829592f, A2 = -0.284496736f, A3 = 1.421413741f;
    const float A4 = -1.453152027f, A5 =  1.061405429f, P  = 0.3275911f;
    float sarg = 0.70710678118654752f * x;
    float a = fabsf(sarg);
    float t = __fdividef(1.f, fmaf(P, a, 1.f));
    float poly = t*fmaf(t, fmaf(t, fmaf(t, fmaf(t, A5, A4), A3), A2), A1);
    float erf = fmaf(-poly, __expf(-a*a), 1.f);
    erf = copysignf(erf, sarg);
    return 0.5f * x * (1.f + erf);
}

// ---------------------------------------------------------------------------
// Kernel 2: output heads, 2 rows per thread, f32x2
// ---------------------------------------------------------------------------
__global__ void __launch_bounds__(256) heads_kernel(
    const float* __restrict__ mhW1, const float* __restrict__ mhb1,
    const float* __restrict__ mhW2, const float* __restrict__ mhb2,
    const float* __restrict__ chW1, const float* __restrict__ chb1,
    const float* __restrict__ chW2, const float* __restrict__ chb2,
    float* __restrict__ out)
{
    __shared__ __align__(16) float w1m[HH*IN_DIM], w1c[HH*IN_DIM];
    __shared__ __align__(16) ull  w2mP[HH*2];
    __shared__ __align__(16) ull  w2cP[HH*5];
    __shared__ float b1m[HH], b1c[HH];
    __shared__ float b2m[MEAN_DIM], b2c[COV_DIM];

    int tid = threadIdx.x;
    for(int i = tid; i < HH*IN_DIM; i += 256){ w1m[i] = mhW1[i]; w1c[i] = chW1[i]; }
    for(int i = tid; i < HH*2; i += 256){
        int u = i >> 1, mp = i & 1;
        w2mP[i] = pack2(mhW2[(2*mp)*HH + u], mhW2[(2*mp+1)*HH + u]);
    }
    for(int i = tid; i < HH*5; i += 256){
        int u = i / 5, vp = i - u*5;
        w2cP[i] = pack2(chW2[(2*vp)*HH + u], chW2[(2*vp+1)*HH + u]);
    }
    if(tid < HH){ b1m[tid] = mhb1[tid]; b1c[tid] = chb1[tid]; }
    if(tid < MEAN_DIM) b2m[tid] = mhb2[tid];
    if(tid < COV_DIM)  b2c[tid] = chb2[tid];
    __syncthreads();

    int r0 = (blockIdx.x*256 + tid)*2;      // rows r0, r0+1
    const ulonglong2* opA = (const ulonglong2*)&g_dec[(size_t)r0*IN_DIM];
    ulonglong2 qa0 = opA[0], qa1 = opA[1], qa2 = opA[2], qa3 = opA[3];
    ulonglong2 qb0 = opA[4], qb1 = opA[5], qb2 = opA[6], qb3 = opA[7];
    ull ovA[8] = { qa0.x,qa0.y,qa1.x,qa1.y,qa2.x,qa2.y,qa3.x,qa3.y };
    ull ovB[8] = { qb0.x,qb0.y,qb1.x,qb1.y,qb2.x,qb2.y,qb3.x,qb3.y };

    ull amA[2], amB[2], acA[5], acB[5];
    amA[0] = amB[0] = pack2(b2m[0], b2m[1]);
    amA[1] = amB[1] = pack2(b2m[2], b2m[3]);
    #pragma unroll
    for(int vp = 0; vp < 5; vp++) acA[vp] = acB[vp] = pack2(b2c[2*vp], b2c[2*vp+1]);

    #pragma unroll 4
    for(int u = 0; u < HH; u++){
        const ull* w1mp = (const ull*)(w1m + u*16);
        const ull* w1cp = (const ull*)(w1c + u*16);
        ull a1A = 0, a1B = 0, a2A = 0, a2B = 0;
        #pragma unroll
        for(int i = 0; i < 8; i++){
            ull wm = w1mp[i], wc = w1cp[i];
            a1A = fma2(ovA[i], wm, a1A);
            a1B = fma2(ovB[i], wm, a1B);
            a2A = fma2(ovA[i], wc, a2A);
            a2B = fma2(ovB[i], wc, a2B);
        }
        float2 f;
        f = unpack2(a1A); float s1A = b1m[u] + f.x + f.y;
        f = unpack2(a1B); float s1B = b1m[u] + f.x + f.y;
        f = unpack2(a2A); float s2A = b1c[u] + f.x + f.y;
        f = unpack2(a2B); float s2B = b1c[u] + f.x + f.y;
        float g1A = gelu_exact(s1A), g1B = gelu_exact(s1B);
        float g2A = gelu_exact(s2A), g2B = gelu_exact(s2B);
        ull g1Ap = pack2(g1A, g1A), g1Bp = pack2(g1B, g1B);
        ull g2Ap = pack2(g2A, g2A), g2Bp = pack2(g2B, g2B);
        ull wm0 = w2mP[u*2], wm1 = w2mP[u*2+1];
        amA[0] = fma2(g1Ap, wm0, amA[0]); amA[1] = fma2(g1Ap, wm1, amA[1]);
        amB[0] = fma2(g1Bp, wm0, amB[0]); amB[1] = fma2(g1Bp, wm1, amB[1]);
        #pragma unroll
        for(int vp = 0; vp < 5; vp++){
            ull wcv = w2cP[u*5+vp];
            acA[vp] = fma2(g2Ap, wcv, acA[vp]);
            acB[vp] = fma2(g2Bp, wcv, acB[vp]);
        }
    }

    // clamp means dims 2,3 to [-1,1]
    { float2 m = unpack2(amA[1]);
      m.x = fminf(fmaxf(m.x, -1.f), 1.f); m.y = fminf(fmaxf(m.y, -1.f), 1.f);
      amA[1] = pack2(m.x, m.y); }
    { float2 m = unpack2(amB[1]);
      m.x = fminf(fmaxf(m.x, -1.f), 1.f); m.y = fminf(fmaxf(m.y, -1.f), 1.f);
      amB[1] = pack2(m.x, m.y); }

    ull* om = (ull*)(out + MEANS_OFF) + (size_t)r0*2;
    om[0] = amA[0]; om[1] = amA[1]; om[2] = amB[0]; om[3] = amB[1];
    ull* oc = (ull*)(out + COVS_OFF) + (size_t)r0*5;
    #pragma unroll
    for(int vp = 0; vp < 5; vp++){ oc[vp] = acA[vp]; oc[5+vp] = acB[vp]; }
}

// ---------------------------------------------------------------------------
extern "C" void kernel_launch(void* const* d_in, const int* in_sizes, int n_in,
                              void* d_out, int out_size)
{
    const float* x     = (const float*)d_in[0];
    const float* trg   = (const float*)d_in[1];
    const float* eWih  = (const float*)d_in[2];
    const float* ebih  = (const float*)d_in[3];
    const float* eWhh  = (const float*)d_in[4];
    const float* ebhh  = (const float*)d_in[5];
    const float* dWih  = (const float*)d_in[6];
    const float* dbih  = (const float*)d_in[7];
    const float* dWhh  = (const float*)d_in[8];
    const float* dbhh  = (const float*)d_in[9];
    const float* outW  = (const float*)d_in[10];
    const float* outb  = (const float*)d_in[11];
    const float* embW  = (const float*)d_in[12];
    const float* embb  = (const float*)d_in[13];
    const float* mhW1  = (const float*)d_in[14];
    const float* mhb1  = (const float*)d_in[15];
    const float* mhW2  = (const float*)d_in[16];
    const float* mhb2  = (const float*)d_in[17];
    const float* chW1  = (const float*)d_in[18];
    const float* chb1  = (const float*)d_in[19];
    const float* chW2  = (const float*)d_in[20];
    const float* chb2  = (const float*)d_in[21];

    cudaFuncSetAttribute(seq_kernel, cudaFuncAttributeMaxDynamicSharedMemorySize,
                         (int)sizeof(Smem));

    seq_kernel<<<GRID1, THREADS1, sizeof(Smem)>>>(
        x, trg, eWih, ebih, eWhh, ebhh, dWih, dbih, dWhh, dbhh,
        outW, outb, embW, embb);

    heads_kernel<<<(BB*SEQ_LEN)/512, 256>>>(
        mhW1, mhb1, mhW2, mhb2, chW1, chb1, chW2, chb2, (float*)d_out);
}